// round 15
// baseline (speedup 1.0000x reference)
#include <cuda_runtime.h>
#include <cuda_fp16.h>
#include <math.h>
#include <stdint.h>

// ---------------- problem constants ----------------
#define BSZ   16
#define A_N   32
#define G_N   512
#define S_N   4096
#define M_N   8
#define D_N   512
#define BS    (BSZ * S_N)      // 65536 rows
#define NGATE 1536
#define SPECT 512

// ---------------- scratch (device globals) ---------------------------------
__device__ __align__(16) __half g_pref[5 * 20 * NGATE];      // fp16 prefix table
__device__ int   g_counts[BS * 5];
__device__ __align__(16) __half g_ghh[(size_t)BS * NGATE];   // gh fp16 (201 MB)
__device__ float g_x3[(size_t)BS * D_N];                     // x3 fp32 (MLP3 out)
__device__ float g_scores[BS];
__device__ __align__(16) __half g_a[(size_t)BS * G_N];       // activations (fp16)
__device__ __align__(16) __half g_b[(size_t)BS * G_N];
__device__ __align__(16) __half g_whh_h[NGATE * G_N];
__device__ __align__(16) __half g_w1_h[D_N * G_N];
__device__ __align__(16) __half g_w2a_h[D_N * G_N];
__device__ __align__(16) __half g_w2b_h[D_N * G_N];

// ---------------- helpers ---------------------------------------------------
__device__ __forceinline__ uint32_t smem_u32(const void* p) {
    uint32_t a;
    asm("{ .reg .u64 t; cvta.to.shared.u64 t, %1; cvt.u32.u64 %0, t; }" : "=r"(a) : "l"(p));
    return a;
}
__device__ __forceinline__ void ldsm4(uint32_t r[4], uint32_t addr) {
    asm volatile("ldmatrix.sync.aligned.m8n8.x4.shared.b16 {%0,%1,%2,%3}, [%4];"
        : "=r"(r[0]), "=r"(r[1]), "=r"(r[2]), "=r"(r[3]) : "r"(addr));
}
__device__ __forceinline__ void mma_f16(float c[4], const uint32_t a[4], const uint32_t b[2]) {
    asm volatile("mma.sync.aligned.m16n8k16.row.col.f32.f16.f16.f32 "
        "{%0,%1,%2,%3}, {%4,%5,%6,%7}, {%8,%9}, {%0,%1,%2,%3};"
        : "+f"(c[0]), "+f"(c[1]), "+f"(c[2]), "+f"(c[3])
        : "r"(a[0]), "r"(a[1]), "r"(a[2]), "r"(a[3]), "r"(b[0]), "r"(b[1]));
}
#define CP16(dst, src) asm volatile("cp.async.cg.shared.global [%0], [%1], 16;" :: "r"(dst), "l"(src))
#define CPCOMMIT()     asm volatile("cp.async.commit_group;" ::: "memory")
__device__ __forceinline__ void cp_wait1() { asm volatile("cp.async.wait_group 1;" ::: "memory"); }
__device__ __forceinline__ void cp_wait0() { asm volatile("cp.async.wait_group 0;" ::: "memory"); }

#define TB (128 * 40 * 2)               // 10240 B per tile (rows padded to 40 halves)
#define SMEM_DYN (6 * TB)               // 3 stages x 2 tiles = 61440 B

// ---------------- setup: weights -> fp16 ------------------------------------
__global__ void k_setup(const float* __restrict__ W_hh, const float* __restrict__ W1,
                        const float* __restrict__ W2a, const float* __restrict__ W2b)
{
    int i = blockIdx.x * 256 + threadIdx.x;
    const int NW = NGATE * G_N;
    const int ND = D_N * G_N;
    if (i < NW) {
        g_whh_h[i] = __float2half_rn(W_hh[i]);
        return;
    }
    i -= NW;
    if (i < 3 * ND) {
        const float* src = (i < ND) ? W1 : (i < 2 * ND ? W2a : W2b);
        __half* dh = (i < ND) ? g_w1_h : (i < 2 * ND ? g_w2a_h : g_w2b_h);
        int k = i % ND;
        dh[k] = __float2half_rn(src[k]);
    }
}

// ---------------- prefix-sum W_ih columns (fp32 accum -> fp16 store) --------
__global__ void k_prefix(const float* __restrict__ W_ih) {
    int o = blockIdx.x * blockDim.x + threadIdx.x;
    if (o >= NGATE) return;
    #pragma unroll
    for (int g = 0; g < 5; g++) {
        float acc = 0.f;
        #pragma unroll
        for (int j = 0; j < 20; j++) {
            acc += W_ih[o * 100 + g * 20 + j];
            g_pref[(g * 20 + j) * NGATE + o] = __float2half_rn(acc);
        }
    }
}

// ---------------- kernel 1: swvs + counts + layernorm -> fp16 ---------------
__global__ __launch_bounds__(256) void k_pre(
    const float* __restrict__ vf, const float* __restrict__ mask,
    const float* __restrict__ eo, const float* __restrict__ subsets,
    const float* __restrict__ lng, const float* __restrict__ lnb)
{
    extern __shared__ float vfs[];
    __shared__ float s_lng[G_N], s_lnb[G_N];
    int b = blockIdx.y;
    int chunk = blockIdx.x;
    int tid = threadIdx.x;

    const float4* vf4 = (const float4*)(vf + (size_t)b * A_N * G_N);
    float4* vfs4 = (float4*)vfs;
    for (int i = tid; i < A_N * G_N / 4; i += 256) {
        float4 v = vf4[i];
        float m = mask[b * A_N + (i * 4) / G_N];
        v.x *= m; v.y *= m; v.z *= m; v.w *= m;
        vfs4[i] = v;
    }
    for (int i = tid; i < G_N; i += 256) { s_lng[i] = lng[i]; s_lnb[i] = lnb[i]; }
    __syncthreads();

    int warp = tid >> 5, lane = tid & 31;
    for (int it = 0; it < 8; it++) {
        int s = chunk * 64 + it * 8 + warp;
        int row = b * S_N + s;
        float as = subsets[(size_t)row * A_N + lane];
        float m  = mask[b * A_N + lane];
        float sm = as * m;

        float ss = sm;
        #pragma unroll
        for (int o = 16; o; o >>= 1) ss += __shfl_xor_sync(0xffffffffu, ss, o);

        #pragma unroll
        for (int e = 0; e < 5; e++) {
            float c = as * eo[(b * A_N + lane) * 5 + e];
            #pragma unroll
            for (int o = 16; o; o >>= 1) c += __shfl_xor_sync(0xffffffffu, c, o);
            if (lane == e) {
                int v = (int)c;
                v = v < 0 ? 0 : (v > 19 ? 19 : v);
                g_counts[row * 5 + e] = v;
            }
        }

        float inv_ss = 1.0f / (ss + 1e-4f);

        float acc[16];
        #pragma unroll
        for (int i = 0; i < 16; i++) acc[i] = 0.f;
        #pragma unroll
        for (int a = 0; a < A_N; a++) {
            float sv = __shfl_sync(0xffffffffu, sm, a);
            #pragma unroll
            for (int i = 0; i < 16; i++)
                acc[i] += vfs[a * G_N + lane + 32 * i] * sv;
        }

        float sum = 0.f, sq = 0.f;
        #pragma unroll
        for (int i = 0; i < 16; i++) {
            acc[i] *= inv_ss;
            sum += acc[i];
            sq  += acc[i] * acc[i];
        }
        #pragma unroll
        for (int o = 16; o; o >>= 1) {
            sum += __shfl_xor_sync(0xffffffffu, sum, o);
            sq  += __shfl_xor_sync(0xffffffffu, sq,  o);
        }
        float mean = sum * (1.0f / G_N);
        float var  = sq  * (1.0f / G_N) - mean * mean;
        float inv  = rsqrtf(var + 1e-5f);
        #pragma unroll
        for (int i = 0; i < 16; i++) {
            int gc = lane + 32 * i;
            float v = (acc[i] - mean) * inv * s_lng[gc] + s_lnb[gc];
            g_a[(size_t)row * G_N + gc] = __float2half_rn(v);
        }
    }
}

// ---------------- mma.sync GEMM: C = epi(A @ W^T + bias) -------------------
// CTA 128x128, 512 threads (4m x 4n warps, 32x32 warp tiles), 3-stage
// cp.async pipeline (issue 2 chunks ahead, wait_group 1), single sync/chunk.
// EPI: 1 = relu -> fp16; 2 = relu -> fp32; 3 = fp16+bias (gh).
template<int NTOT, int EPI>
__global__ __launch_bounds__(512, 2) void k_mgemm(
    const __half* __restrict__ A, const __half* __restrict__ W,
    const float* __restrict__ bias,
    float* __restrict__ Cf, __half* __restrict__ Ch)
{
    extern __shared__ char dsm[];
    const int tid = threadIdx.x, lane = tid & 31, wid = tid >> 5;   // 16 warps
    const int wm = wid & 3, wn = wid >> 2;                           // 4m x 4n
    const int bm = blockIdx.y * 128, bn = blockIdx.x * 128;
    const uint32_t sbase = smem_u32(dsm);

    const __half* srcA = A + (size_t)bm * G_N;
    const __half* srcW = W + (size_t)bn * G_N;

    float c[2][4][4];
    #pragma unroll
    for (int i = 0; i < 2; i++)
        #pragma unroll
        for (int j = 0; j < 4; j++)
            #pragma unroll
            for (int q = 0; q < 4; q++) c[i][j][q] = 0.f;

    const int row_l = tid >> 2;       // 0..127
    const int c16   = tid & 3;
    const uint32_t so = row_l * 80 + c16 * 16;
    const size_t   gb = (size_t)row_l * G_N + c16 * 8;

    // prologue: chunks 0,1 into stages 0,1
    CP16(sbase + 0 * TB + so, srcA + gb);
    CP16(sbase + 1 * TB + so, srcW + gb);
    CPCOMMIT();
    CP16(sbase + 2 * TB + so, srcA + gb + 32);
    CP16(sbase + 3 * TB + so, srcW + gb + 32);
    CPCOMMIT();

    const int a_row = wm * 32 + (lane & 7) + ((lane >> 3) & 1) * 8;
    const int a_kad = (lane >> 4) * 8;
    const int w_row = wn * 32 + (lane & 7) + ((lane >> 4) & 1) * 8;
    const int w_kad = ((lane >> 3) & 1) * 8;

    int st = 0;
    #pragma unroll 1
    for (int kc = 0; kc < 16; kc++) {
        if (kc < 15) cp_wait1(); else cp_wait0();
        __syncthreads();
        if (kc + 2 < 16) {
            int ns = st + 2; if (ns >= 3) ns -= 3;
            const int kcol = (kc + 2) * 32;
            CP16(sbase + (ns * 2 + 0) * TB + so, srcA + gb + kcol);
            CP16(sbase + (ns * 2 + 1) * TB + so, srcW + gb + kcol);
            CPCOMMIT();
        }

        const uint32_t tA = sbase + (st * 2) * TB;
        const uint32_t tW = sbase + (st * 2 + 1) * TB;
        #pragma unroll
        for (int ks = 0; ks < 2; ks++) {
            uint32_t ah[2][4];
            #pragma unroll
            for (int mt = 0; mt < 2; mt++) {
                uint32_t ad = tA + ((a_row + mt * 16) * 40 + a_kad + ks * 16) * 2;
                ldsm4(ah[mt], ad);
            }
            #pragma unroll
            for (int np = 0; np < 2; np++) {
                uint32_t bd = tW + ((w_row + np * 16) * 40 + w_kad + ks * 16) * 2;
                uint32_t bh[4];
                ldsm4(bh, bd);
                #pragma unroll
                for (int p = 0; p < 2; p++) {
                    const int nt = np * 2 + p;
                    mma_f16(c[0][nt], ah[0], &bh[p * 2]);
                    mma_f16(c[1][nt], ah[1], &bh[p * 2]);
                }
            }
        }
        st = st + 1; if (st >= 3) st = 0;
    }

    // ---- epilogue
    const int r_base = bm + wm * 32 + (lane >> 2);
    const int c_base = bn + wn * 32 + (lane & 3) * 2;
    #pragma unroll
    for (int mt = 0; mt < 2; mt++) {
        #pragma unroll
        for (int nt = 0; nt < 4; nt++) {
            const int row0 = r_base + mt * 16;
            const int row1 = row0 + 8;
            const int col  = c_base + nt * 8;
            const float b0 = bias[col], b1 = bias[col + 1];
            float v00 = c[mt][nt][0] + b0, v01 = c[mt][nt][1] + b1;
            float v10 = c[mt][nt][2] + b0, v11 = c[mt][nt][3] + b1;
            if (EPI == 1 || EPI == 3) {
                if (EPI == 1) {
                    v00 = fmaxf(v00, 0.f); v01 = fmaxf(v01, 0.f);
                    v10 = fmaxf(v10, 0.f); v11 = fmaxf(v11, 0.f);
                }
                __half2 h0; h0.x = __float2half_rn(v00); h0.y = __float2half_rn(v01);
                __half2 h1; h1.x = __float2half_rn(v10); h1.y = __float2half_rn(v11);
                *(__half2*)&Ch[(size_t)row0 * NTOT + col] = h0;
                *(__half2*)&Ch[(size_t)row1 * NTOT + col] = h1;
            } else {
                if (EPI == 2) {
                    v00 = fmaxf(v00, 0.f); v01 = fmaxf(v01, 0.f);
                    v10 = fmaxf(v10, 0.f); v11 = fmaxf(v11, 0.f);
                }
                float2 o0; o0.x = v00; o0.y = v01;
                float2 o1; o1.x = v10; o1.y = v11;
                *(float2*)&Cf[(size_t)row0 * NTOT + col] = o0;
                *(float2*)&Cf[(size_t)row1 * NTOT + col] = o1;
            }
        }
    }
}

// ---------------- GRU combine (4 rows/block, fp16 gh + fp16 prefix) ----------
__device__ __forceinline__ void ld4(float* d, const float* p) {
    float4 v = *(const float4*)p;
    d[0] = v.x; d[1] = v.y; d[2] = v.z; d[3] = v.w;
}
__device__ __forceinline__ void ldh4(float* d, const __half* p) {
    __half2 a = *(const __half2*)p;
    __half2 b = *(const __half2*)(p + 2);
    d[0] = __half2float(a.x); d[1] = __half2float(a.y);
    d[2] = __half2float(b.x); d[3] = __half2float(b.y);
}
__device__ __forceinline__ void addh4(float* d, const __half* p) {
    __half2 a = *(const __half2*)p;
    __half2 b = *(const __half2*)(p + 2);
    d[0] += __half2float(a.x); d[1] += __half2float(a.y);
    d[2] += __half2float(b.x); d[3] += __half2float(b.y);
}

__global__ __launch_bounds__(512) void k_gru(const float* __restrict__ bih)
{
    int t = threadIdx.x;
    int row = blockIdx.x * 4 + (t >> 7);     // 4 rows per block
    int lt = t & 127;
    __shared__ int cnt[4][5];
    if (lt < 5) cnt[t >> 7][lt] = g_counts[row * 5 + lt];
    __syncthreads();
    const int* cr = cnt[t >> 7];
    const int j = lt * 4;
    const __half* gh = g_ghh + (size_t)row * NGATE;

    float gr[4], gz[4], gn[4];
    ld4(gr, &bih[j]); ld4(gz, &bih[512 + j]); ld4(gn, &bih[1024 + j]);
    #pragma unroll
    for (int g = 0; g < 5; g++) {
        const __half* pg = g_pref + (size_t)(g * 20 + cr[g]) * NGATE;
        addh4(gr, &pg[j]);
        addh4(gz, &pg[512 + j]);
        addh4(gn, &pg[1024 + j]);
    }
    float hr[4], hz[4], hn[4];
    ldh4(hr, &gh[j]); ldh4(hz, &gh[512 + j]); ldh4(hn, &gh[1024 + j]);

    const size_t idx = (size_t)row * G_N + j;
    __half2 hpa = *(const __half2*)&g_a[idx];
    __half2 hpb = *(const __half2*)&g_a[idx + 2];
    float hp[4] = { __half2float(hpa.x), __half2float(hpa.y),
                    __half2float(hpb.x), __half2float(hpb.y) };

    float h[4];
    #pragma unroll
    for (int u = 0; u < 4; u++) {
        float r = 1.f / (1.f + expf(-(gr[u] + hr[u])));
        float z = 1.f / (1.f + expf(-(gz[u] + hz[u])));
        float n = tanhf(gn[u] + r * hn[u]);
        h[u] = (1.f - z) * n + z * hp[u];
    }
    __half2 o0, o1;
    o0.x = __float2half_rn(h[0]); o0.y = __float2half_rn(h[1]);
    o1.x = __float2half_rn(h[2]); o1.y = __float2half_rn(h[3]);
    *(__half2*)&g_b[idx]     = o0;
    *(__half2*)&g_b[idx + 2] = o1;
}

// ---------------- layernorm + score ----------------------------------------
__global__ __launch_bounds__(256) void k_lnscore(
    const float* __restrict__ x3,
    const float* __restrict__ lng, const float* __restrict__ lnb,
    const float* __restrict__ Ws, const float* __restrict__ bsc)
{
    int warp = threadIdx.x >> 5, lane = threadIdx.x & 31;
    int row = blockIdx.x * 8 + warp;
    const float* x = x3 + (size_t)row * D_N;
    float v[16];
    float sum = 0.f, sq = 0.f;
    #pragma unroll
    for (int i = 0; i < 16; i++) {
        v[i] = x[lane + 32 * i];
        sum += v[i]; sq += v[i] * v[i];
    }
    #pragma unroll
    for (int o = 16; o; o >>= 1) {
        sum += __shfl_xor_sync(0xffffffffu, sum, o);
        sq  += __shfl_xor_sync(0xffffffffu, sq,  o);
    }
    float mean = sum * (1.0f / D_N);
    float var  = sq  * (1.0f / D_N) - mean * mean;
    float inv  = rsqrtf(var + 1e-5f);
    float sc = 0.f;
    #pragma unroll
    for (int i = 0; i < 16; i++) {
        int cc = lane + 32 * i;
        sc += ((v[i] - mean) * inv * lng[cc] + lnb[cc]) * Ws[cc];
    }
    #pragma unroll
    for (int o = 16; o; o >>= 1) sc += __shfl_xor_sync(0xffffffffu, sc, o);
    if (lane == 0) g_scores[row] = sc + bsc[0];
}

// ---------------- softmax ---------------------------------------------------
__global__ __launch_bounds__(1024) void k_softmax(float* __restrict__ out)
{
    int b = blockIdx.x, tid = threadIdx.x;
    __shared__ float red[32];
    __shared__ float red2[32];
    float v[4];
    #pragma unroll
    for (int i = 0; i < 4; i++) v[i] = g_scores[b * S_N + tid + 1024 * i];
    float mx = fmaxf(fmaxf(v[0], v[1]), fmaxf(v[2], v[3]));
    #pragma unroll
    for (int o = 16; o; o >>= 1) mx = fmaxf(mx, __shfl_xor_sync(0xffffffffu, mx, o));
    if ((tid & 31) == 0) red[tid >> 5] = mx;
    __syncthreads();
    if (tid < 32) {
        float m2 = red[tid];
        #pragma unroll
        for (int o = 16; o; o >>= 1) m2 = fmaxf(m2, __shfl_xor_sync(0xffffffffu, m2, o));
        red[tid] = m2;
    }
    __syncthreads();
    mx = red[0];
    float s = 0.f;
    #pragma unroll
    for (int i = 0; i < 4; i++) { v[i] = expf(v[i] - mx); s += v[i]; }
    #pragma unroll
    for (int o = 16; o; o >>= 1) s += __shfl_xor_sync(0xffffffffu, s, o);
    if ((tid & 31) == 0) red2[tid >> 5] = s;
    __syncthreads();
    if (tid < 32) {
        float s2 = red2[tid];
        #pragma unroll
        for (int o = 16; o; o >>= 1) s2 += __shfl_xor_sync(0xffffffffu, s2, o);
        red2[tid] = s2;
    }
    __syncthreads();
    float invs = 1.f / red2[0];
    #pragma unroll
    for (int i = 0; i < 4; i++)
        out[BSZ * SPECT + b * S_N + tid + 1024 * i] = v[i] * invs;
}

// ---------------- scatter ---------------------------------------------------
__global__ void k_scatter(const float* __restrict__ peaks, float* __restrict__ out)
{
    int id = blockIdx.x * blockDim.x + threadIdx.x;
    if (id >= BS * M_N) return;
    int rs = id / M_N;
    int b = rs / S_N;
    float mass  = peaks[(size_t)id * 2];
    float inten = peaks[(size_t)id * 2 + 1];
    int bin = (int)rintf(mass);
    bin = bin < 0 ? 0 : (bin > SPECT - 1 ? SPECT - 1 : bin);
    float p = out[BSZ * SPECT + rs];
    atomicAdd(&out[b * SPECT + bin], inten * p);
}

// ---------------- launch ---------------------------------------------------
extern "C" void kernel_launch(void* const* d_in, const int* in_sizes, int n_in,
                              void* d_out, int out_size)
{
    const float* vf      = (const float*)d_in[0];
    const float* mask    = (const float*)d_in[1];
    const float* eo      = (const float*)d_in[2];
    const float* subsets = (const float*)d_in[4];
    const float* peaks   = (const float*)d_in[5];
    const float* lnsub_g = (const float*)d_in[6];
    const float* lnsub_b = (const float*)d_in[7];
    const float* W_ih    = (const float*)d_in[8];
    const float* W_hh    = (const float*)d_in[9];
    const float* b_ih    = (const float*)d_in[10];
    const float* b_hh    = (const float*)d_in[11];
    const float* W1      = (const float*)d_in[12];
    const float* b1      = (const float*)d_in[13];
    const float* W2a     = (const float*)d_in[14];
    const float* b2a     = (const float*)d_in[15];
    const float* W2b     = (const float*)d_in[16];
    const float* b2b     = (const float*)d_in[17];
    const float* lnpre_g = (const float*)d_in[18];
    const float* lnpre_b = (const float*)d_in[19];
    const float* Ws      = (const float*)d_in[20];
    const float* bsc     = (const float*)d_in[21];
    float* out = (float*)d_out;

    __half *pa, *pb, *pGHH;
    __half *whh_h, *w1_h, *w2a_h, *w2b_h;
    float* pX3;
    cudaGetSymbolAddress((void**)&pa, g_a);
    cudaGetSymbolAddress((void**)&pb, g_b);
    cudaGetSymbolAddress((void**)&pGHH, g_ghh);
    cudaGetSymbolAddress((void**)&pX3, g_x3);
    cudaGetSymbolAddress((void**)&whh_h, g_whh_h);
    cudaGetSymbolAddress((void**)&w1_h, g_w1_h);
    cudaGetSymbolAddress((void**)&w2a_h, g_w2a_h);
    cudaGetSymbolAddress((void**)&w2b_h, g_w2b_h);

    cudaMemsetAsync(d_out, 0, BSZ * SPECT * sizeof(float), 0);

    k_setup<<<(NGATE * G_N + 3 * D_N * G_N + 255) / 256, 256>>>(W_hh, W1, W2a, W2b);
    k_prefix<<<6, 256>>>(W_ih);

    cudaFuncSetAttribute(k_pre, cudaFuncAttributeMaxDynamicSharedMemorySize, 65536);
    k_pre<<<dim3(64, 16), 256, 65536>>>(vf, mask, eo, subsets, lnsub_g, lnsub_b);

    cudaFuncSetAttribute(k_mgemm<1536, 3>, cudaFuncAttributeMaxDynamicSharedMemorySize, SMEM_DYN);
    cudaFuncSetAttribute(k_mgemm<512, 1>,  cudaFuncAttributeMaxDynamicSharedMemorySize, SMEM_DYN);
    cudaFuncSetAttribute(k_mgemm<512, 2>,  cudaFuncAttributeMaxDynamicSharedMemorySize, SMEM_DYN);

    // gh = normed @ W_hh^T + b_hh  (fp16 out)
    k_mgemm<1536, 3><<<dim3(12, 512), 512, SMEM_DYN>>>(
        pa, whh_h, b_hh, nullptr, pGHH);

    // GRU combine -> h (fp16 in g_b)
    k_gru<<<BS / 4, 512>>>(b_ih);

    // MLP
    k_mgemm<512, 1><<<dim3(4, 512), 512, SMEM_DYN>>>(
        pb, w1_h, b1, nullptr, pa);
    k_mgemm<512, 1><<<dim3(4, 512), 512, SMEM_DYN>>>(
        pa, w2a_h, b2a, nullptr, pb);
    k_mgemm<512, 2><<<dim3(4, 512), 512, SMEM_DYN>>>(
        pb, w2b_h, b2b, pX3, nullptr);

    // tail
    k_lnscore<<<BS / 8, 256>>>(pX3, lnpre_g, lnpre_b, Ws, bsc);
    k_softmax<<<BSZ, 1024>>>(out);
    k_scatter<<<(BS * M_N + 255) / 256, 256>>>(peaks, out);
}

// round 16
// speedup vs baseline: 1.5491x; 1.5491x over previous
#include <cuda_runtime.h>
#include <cuda_fp16.h>
#include <math.h>
#include <stdint.h>

// ---------------- problem constants ----------------
#define BSZ   16
#define A_N   32
#define G_N   512
#define S_N   4096
#define M_N   8
#define D_N   512
#define BS    (BSZ * S_N)      // 65536 rows
#define NGATE 1536
#define SPECT 512

// ---------------- scratch (device globals) ---------------------------------
__device__ __align__(16) __half g_pref[5 * 20 * NGATE];      // fp16 prefix table
__device__ int   g_counts[BS * 5];
__device__ __align__(16) __half g_ghh[(size_t)BS * NGATE];   // gh fp16 (201 MB)
__device__ float g_x3[(size_t)BS * D_N];                     // x3 fp32 (MLP3 out)
__device__ float g_scores[BS];
__device__ __align__(16) __half g_a[(size_t)BS * G_N];       // activations (fp16)
__device__ __align__(16) __half g_b[(size_t)BS * G_N];
__device__ __align__(16) __half g_whh_h[NGATE * G_N];
__device__ __align__(16) __half g_w1_h[D_N * G_N];
__device__ __align__(16) __half g_w2a_h[D_N * G_N];
__device__ __align__(16) __half g_w2b_h[D_N * G_N];

// ---------------- helpers ---------------------------------------------------
__device__ __forceinline__ uint32_t smem_u32(const void* p) {
    uint32_t a;
    asm("{ .reg .u64 t; cvta.to.shared.u64 t, %1; cvt.u32.u64 %0, t; }" : "=r"(a) : "l"(p));
    return a;
}
__device__ __forceinline__ void ldsm4(uint32_t r[4], uint32_t addr) {
    asm volatile("ldmatrix.sync.aligned.m8n8.x4.shared.b16 {%0,%1,%2,%3}, [%4];"
        : "=r"(r[0]), "=r"(r[1]), "=r"(r[2]), "=r"(r[3]) : "r"(addr));
}
__device__ __forceinline__ void mma_f16(float c[4], const uint32_t a[4], const uint32_t b[2]) {
    asm volatile("mma.sync.aligned.m16n8k16.row.col.f32.f16.f16.f32 "
        "{%0,%1,%2,%3}, {%4,%5,%6,%7}, {%8,%9}, {%0,%1,%2,%3};"
        : "+f"(c[0]), "+f"(c[1]), "+f"(c[2]), "+f"(c[3])
        : "r"(a[0]), "r"(a[1]), "r"(a[2]), "r"(a[3]), "r"(b[0]), "r"(b[1]));
}
#define CP16(dst, src) asm volatile("cp.async.cg.shared.global [%0], [%1], 16;" :: "r"(dst), "l"(src))
#define CPCOMMIT()     asm volatile("cp.async.commit_group;" ::: "memory")
__device__ __forceinline__ void cp_wait0() { asm volatile("cp.async.wait_group 0;" ::: "memory"); }

#define TB (128 * 40 * 2)               // 10240 B per tile (rows padded to 40 halves)
#define SMEM_DYN (4 * TB)               // 2 stages x 2 tiles = 40960 B

// ---------------- setup: weights -> fp16 ------------------------------------
__global__ void k_setup(const float* __restrict__ W_hh, const float* __restrict__ W1,
                        const float* __restrict__ W2a, const float* __restrict__ W2b)
{
    int i = blockIdx.x * 256 + threadIdx.x;
    const int NW = NGATE * G_N;
    const int ND = D_N * G_N;
    if (i < NW) {
        g_whh_h[i] = __float2half_rn(W_hh[i]);
        return;
    }
    i -= NW;
    if (i < 3 * ND) {
        const float* src = (i < ND) ? W1 : (i < 2 * ND ? W2a : W2b);
        __half* dh = (i < ND) ? g_w1_h : (i < 2 * ND ? g_w2a_h : g_w2b_h);
        int k = i % ND;
        dh[k] = __float2half_rn(src[k]);
    }
}

// ---------------- prefix-sum W_ih columns (fp32 accum -> fp16 store) --------
__global__ void k_prefix(const float* __restrict__ W_ih) {
    int o = blockIdx.x * blockDim.x + threadIdx.x;
    if (o >= NGATE) return;
    #pragma unroll
    for (int g = 0; g < 5; g++) {
        float acc = 0.f;
        #pragma unroll
        for (int j = 0; j < 20; j++) {
            acc += W_ih[o * 100 + g * 20 + j];
            g_pref[(g * 20 + j) * NGATE + o] = __float2half_rn(acc);
        }
    }
}

// ---------------- kernel 1: swvs + counts + layernorm -> fp16 ---------------
__global__ __launch_bounds__(256) void k_pre(
    const float* __restrict__ vf, const float* __restrict__ mask,
    const float* __restrict__ eo, const float* __restrict__ subsets,
    const float* __restrict__ lng, const float* __restrict__ lnb)
{
    extern __shared__ float vfs[];
    __shared__ float s_lng[G_N], s_lnb[G_N];
    int b = blockIdx.y;
    int chunk = blockIdx.x;
    int tid = threadIdx.x;

    const float4* vf4 = (const float4*)(vf + (size_t)b * A_N * G_N);
    float4* vfs4 = (float4*)vfs;
    for (int i = tid; i < A_N * G_N / 4; i += 256) {
        float4 v = vf4[i];
        float m = mask[b * A_N + (i * 4) / G_N];
        v.x *= m; v.y *= m; v.z *= m; v.w *= m;
        vfs4[i] = v;
    }
    for (int i = tid; i < G_N; i += 256) { s_lng[i] = lng[i]; s_lnb[i] = lnb[i]; }
    __syncthreads();

    int warp = tid >> 5, lane = tid & 31;
    for (int it = 0; it < 8; it++) {
        int s = chunk * 64 + it * 8 + warp;
        int row = b * S_N + s;
        float as = subsets[(size_t)row * A_N + lane];
        float m  = mask[b * A_N + lane];
        float sm = as * m;

        float ss = sm;
        #pragma unroll
        for (int o = 16; o; o >>= 1) ss += __shfl_xor_sync(0xffffffffu, ss, o);

        #pragma unroll
        for (int e = 0; e < 5; e++) {
            float c = as * eo[(b * A_N + lane) * 5 + e];
            #pragma unroll
            for (int o = 16; o; o >>= 1) c += __shfl_xor_sync(0xffffffffu, c, o);
            if (lane == e) {
                int v = (int)c;
                v = v < 0 ? 0 : (v > 19 ? 19 : v);
                g_counts[row * 5 + e] = v;
            }
        }

        float inv_ss = 1.0f / (ss + 1e-4f);

        float acc[16];
        #pragma unroll
        for (int i = 0; i < 16; i++) acc[i] = 0.f;
        #pragma unroll
        for (int a = 0; a < A_N; a++) {
            float sv = __shfl_sync(0xffffffffu, sm, a);
            #pragma unroll
            for (int i = 0; i < 16; i++)
                acc[i] += vfs[a * G_N + lane + 32 * i] * sv;
        }

        float sum = 0.f, sq = 0.f;
        #pragma unroll
        for (int i = 0; i < 16; i++) {
            acc[i] *= inv_ss;
            sum += acc[i];
            sq  += acc[i] * acc[i];
        }
        #pragma unroll
        for (int o = 16; o; o >>= 1) {
            sum += __shfl_xor_sync(0xffffffffu, sum, o);
            sq  += __shfl_xor_sync(0xffffffffu, sq,  o);
        }
        float mean = sum * (1.0f / G_N);
        float var  = sq  * (1.0f / G_N) - mean * mean;
        float inv  = rsqrtf(var + 1e-5f);
        #pragma unroll
        for (int i = 0; i < 16; i++) {
            int gc = lane + 32 * i;
            float v = (acc[i] - mean) * inv * s_lng[gc] + s_lnb[gc];
            g_a[(size_t)row * G_N + gc] = __float2half_rn(v);
        }
    }
}

// ---------------- mma.sync GEMM: C = epi(A @ W^T + bias) -------------------
// CTA 128x128, 512 threads (4m x 4n warps, 32x32 warp tiles), 2-stage,
// single-__syncthreads mainloop. Pure fp16 A and W (1 fp32-acc MMA per frag).
// EPI: 1 = relu -> fp16; 2 = relu -> fp32; 3 = fp16+bias (gh).
template<int NTOT, int EPI>
__global__ __launch_bounds__(512, 2) void k_mgemm(
    const __half* __restrict__ A, const __half* __restrict__ W,
    const float* __restrict__ bias,
    float* __restrict__ Cf, __half* __restrict__ Ch)
{
    extern __shared__ char dsm[];
    const int tid = threadIdx.x, lane = tid & 31, wid = tid >> 5;   // 16 warps
    const int wm = wid & 3, wn = wid >> 2;                           // 4m x 4n
    const int bm = blockIdx.y * 128, bn = blockIdx.x * 128;
    const uint32_t sbase = smem_u32(dsm);

    const __half* srcs[2] = { A + (size_t)bm * G_N, W + (size_t)bn * G_N };

    float c[2][4][4];
    #pragma unroll
    for (int i = 0; i < 2; i++)
        #pragma unroll
        for (int j = 0; j < 4; j++)
            #pragma unroll
            for (int q = 0; q < 4; q++) c[i][j][q] = 0.f;

    const int row_l = tid >> 2;       // 0..127
    const int c16   = tid & 3;
    const uint32_t so = row_l * 80 + c16 * 16;
    const size_t   gb = (size_t)row_l * G_N + c16 * 8;

    // prologue: chunk 0 into stage 0
    CP16(sbase + 0 * TB + so, srcs[0] + gb);
    CP16(sbase + 1 * TB + so, srcs[1] + gb);
    CPCOMMIT();

    const int a_row = wm * 32 + (lane & 7) + ((lane >> 3) & 1) * 8;
    const int a_kad = (lane >> 4) * 8;
    const int w_row = wn * 32 + (lane & 7) + ((lane >> 4) & 1) * 8;
    const int w_kad = ((lane >> 3) & 1) * 8;

    #pragma unroll 1
    for (int kc = 0; kc < 16; kc++) {
        const int s = kc & 1;
        cp_wait0();
        __syncthreads();
        if (kc + 1 < 16) {
            const int ns = s ^ 1;
            const int kcol = (kc + 1) * 32;
            CP16(sbase + (ns * 2 + 0) * TB + so, srcs[0] + gb + kcol);
            CP16(sbase + (ns * 2 + 1) * TB + so, srcs[1] + gb + kcol);
            CPCOMMIT();
        }

        const uint32_t tA = sbase + (s * 2) * TB;
        const uint32_t tW = sbase + (s * 2 + 1) * TB;
        #pragma unroll
        for (int ks = 0; ks < 2; ks++) {
            uint32_t ah[2][4];
            #pragma unroll
            for (int mt = 0; mt < 2; mt++) {
                uint32_t ad = tA + ((a_row + mt * 16) * 40 + a_kad + ks * 16) * 2;
                ldsm4(ah[mt], ad);
            }
            #pragma unroll
            for (int np = 0; np < 2; np++) {
                uint32_t bd = tW + ((w_row + np * 16) * 40 + w_kad + ks * 16) * 2;
                uint32_t bh[4];
                ldsm4(bh, bd);
                #pragma unroll
                for (int p = 0; p < 2; p++) {
                    const int nt = np * 2 + p;
                    mma_f16(c[0][nt], ah[0], &bh[p * 2]);
                    mma_f16(c[1][nt], ah[1], &bh[p * 2]);
                }
            }
        }
    }

    // ---- epilogue
    const int r_base = bm + wm * 32 + (lane >> 2);
    const int c_base = bn + wn * 32 + (lane & 3) * 2;
    #pragma unroll
    for (int mt = 0; mt < 2; mt++) {
        #pragma unroll
        for (int nt = 0; nt < 4; nt++) {
            const int row0 = r_base + mt * 16;
            const int row1 = row0 + 8;
            const int col  = c_base + nt * 8;
            const float b0 = bias[col], b1 = bias[col + 1];
            float v00 = c[mt][nt][0] + b0, v01 = c[mt][nt][1] + b1;
            float v10 = c[mt][nt][2] + b0, v11 = c[mt][nt][3] + b1;
            if (EPI == 1 || EPI == 3) {
                if (EPI == 1) {
                    v00 = fmaxf(v00, 0.f); v01 = fmaxf(v01, 0.f);
                    v10 = fmaxf(v10, 0.f); v11 = fmaxf(v11, 0.f);
                }
                __half2 h0; h0.x = __float2half_rn(v00); h0.y = __float2half_rn(v01);
                __half2 h1; h1.x = __float2half_rn(v10); h1.y = __float2half_rn(v11);
                *(__half2*)&Ch[(size_t)row0 * NTOT + col] = h0;
                *(__half2*)&Ch[(size_t)row1 * NTOT + col] = h1;
            } else {
                if (EPI == 2) {
                    v00 = fmaxf(v00, 0.f); v01 = fmaxf(v01, 0.f);
                    v10 = fmaxf(v10, 0.f); v11 = fmaxf(v11, 0.f);
                }
                float2 o0; o0.x = v00; o0.y = v01;
                float2 o1; o1.x = v10; o1.y = v11;
                *(float2*)&Cf[(size_t)row0 * NTOT + col] = o0;
                *(float2*)&Cf[(size_t)row1 * NTOT + col] = o1;
            }
        }
    }
}

// ---------------- GRU combine (4 rows/block, fp16 gh + fp16 prefix) ----------
__device__ __forceinline__ void ld4(float* d, const float* p) {
    float4 v = *(const float4*)p;
    d[0] = v.x; d[1] = v.y; d[2] = v.z; d[3] = v.w;
}
__device__ __forceinline__ void ldh4(float* d, const __half* p) {
    __half2 a = *(const __half2*)p;
    __half2 b = *(const __half2*)(p + 2);
    d[0] = __half2float(a.x); d[1] = __half2float(a.y);
    d[2] = __half2float(b.x); d[3] = __half2float(b.y);
}
__device__ __forceinline__ void addh4(float* d, const __half* p) {
    __half2 a = *(const __half2*)p;
    __half2 b = *(const __half2*)(p + 2);
    d[0] += __half2float(a.x); d[1] += __half2float(a.y);
    d[2] += __half2float(b.x); d[3] += __half2float(b.y);
}

__global__ __launch_bounds__(512) void k_gru(const float* __restrict__ bih)
{
    int t = threadIdx.x;
    int row = blockIdx.x * 4 + (t >> 7);     // 4 rows per block
    int lt = t & 127;
    __shared__ int cnt[4][5];
    if (lt < 5) cnt[t >> 7][lt] = g_counts[row * 5 + lt];
    __syncthreads();
    const int* cr = cnt[t >> 7];
    const int j = lt * 4;
    const __half* gh = g_ghh + (size_t)row * NGATE;

    float gr[4], gz[4], gn[4];
    ld4(gr, &bih[j]); ld4(gz, &bih[512 + j]); ld4(gn, &bih[1024 + j]);
    #pragma unroll
    for (int g = 0; g < 5; g++) {
        const __half* pg = g_pref + (size_t)(g * 20 + cr[g]) * NGATE;
        addh4(gr, &pg[j]);
        addh4(gz, &pg[512 + j]);
        addh4(gn, &pg[1024 + j]);
    }
    float hr[4], hz[4], hn[4];
    ldh4(hr, &gh[j]); ldh4(hz, &gh[512 + j]); ldh4(hn, &gh[1024 + j]);

    const size_t idx = (size_t)row * G_N + j;
    __half2 hpa = *(const __half2*)&g_a[idx];
    __half2 hpb = *(const __half2*)&g_a[idx + 2];
    float hp[4] = { __half2float(hpa.x), __half2float(hpa.y),
                    __half2float(hpb.x), __half2float(hpb.y) };

    float h[4];
    #pragma unroll
    for (int u = 0; u < 4; u++) {
        float r = 1.f / (1.f + expf(-(gr[u] + hr[u])));
        float z = 1.f / (1.f + expf(-(gz[u] + hz[u])));
        float n = tanhf(gn[u] + r * hn[u]);
        h[u] = (1.f - z) * n + z * hp[u];
    }
    __half2 o0, o1;
    o0.x = __float2half_rn(h[0]); o0.y = __float2half_rn(h[1]);
    o1.x = __float2half_rn(h[2]); o1.y = __float2half_rn(h[3]);
    *(__half2*)&g_b[idx]     = o0;
    *(__half2*)&g_b[idx + 2] = o1;
}

// ---------------- layernorm + score ----------------------------------------
__global__ __launch_bounds__(256) void k_lnscore(
    const float* __restrict__ x3,
    const float* __restrict__ lng, const float* __restrict__ lnb,
    const float* __restrict__ Ws, const float* __restrict__ bsc)
{
    int warp = threadIdx.x >> 5, lane = threadIdx.x & 31;
    int row = blockIdx.x * 8 + warp;
    const float* x = x3 + (size_t)row * D_N;
    float v[16];
    float sum = 0.f, sq = 0.f;
    #pragma unroll
    for (int i = 0; i < 16; i++) {
        v[i] = x[lane + 32 * i];
        sum += v[i]; sq += v[i] * v[i];
    }
    #pragma unroll
    for (int o = 16; o; o >>= 1) {
        sum += __shfl_xor_sync(0xffffffffu, sum, o);
        sq  += __shfl_xor_sync(0xffffffffu, sq,  o);
    }
    float mean = sum * (1.0f / D_N);
    float var  = sq  * (1.0f / D_N) - mean * mean;
    float inv  = rsqrtf(var + 1e-5f);
    float sc = 0.f;
    #pragma unroll
    for (int i = 0; i < 16; i++) {
        int cc = lane + 32 * i;
        sc += ((v[i] - mean) * inv * lng[cc] + lnb[cc]) * Ws[cc];
    }
    #pragma unroll
    for (int o = 16; o; o >>= 1) sc += __shfl_xor_sync(0xffffffffu, sc, o);
    if (lane == 0) g_scores[row] = sc + bsc[0];
}

// ---------------- softmax ---------------------------------------------------
__global__ __launch_bounds__(1024) void k_softmax(float* __restrict__ out)
{
    int b = blockIdx.x, tid = threadIdx.x;
    __shared__ float red[32];
    __shared__ float red2[32];
    float v[4];
    #pragma unroll
    for (int i = 0; i < 4; i++) v[i] = g_scores[b * S_N + tid + 1024 * i];
    float mx = fmaxf(fmaxf(v[0], v[1]), fmaxf(v[2], v[3]));
    #pragma unroll
    for (int o = 16; o; o >>= 1) mx = fmaxf(mx, __shfl_xor_sync(0xffffffffu, mx, o));
    if ((tid & 31) == 0) red[tid >> 5] = mx;
    __syncthreads();
    if (tid < 32) {
        float m2 = red[tid];
        #pragma unroll
        for (int o = 16; o; o >>= 1) m2 = fmaxf(m2, __shfl_xor_sync(0xffffffffu, m2, o));
        red[tid] = m2;
    }
    __syncthreads();
    mx = red[0];
    float s = 0.f;
    #pragma unroll
    for (int i = 0; i < 4; i++) { v[i] = expf(v[i] - mx); s += v[i]; }
    #pragma unroll
    for (int o = 16; o; o >>= 1) s += __shfl_xor_sync(0xffffffffu, s, o);
    if ((tid & 31) == 0) red2[tid >> 5] = s;
    __syncthreads();
    if (tid < 32) {
        float s2 = red2[tid];
        #pragma unroll
        for (int o = 16; o; o >>= 1) s2 += __shfl_xor_sync(0xffffffffu, s2, o);
        red2[tid] = s2;
    }
    __syncthreads();
    float invs = 1.f / red2[0];
    #pragma unroll
    for (int i = 0; i < 4; i++)
        out[BSZ * SPECT + b * S_N + tid + 1024 * i] = v[i] * invs;
}

// ---------------- scatter ---------------------------------------------------
__global__ void k_scatter(const float* __restrict__ peaks, float* __restrict__ out)
{
    int id = blockIdx.x * blockDim.x + threadIdx.x;
    if (id >= BS * M_N) return;
    int rs = id / M_N;
    int b = rs / S_N;
    float mass  = peaks[(size_t)id * 2];
    float inten = peaks[(size_t)id * 2 + 1];
    int bin = (int)rintf(mass);
    bin = bin < 0 ? 0 : (bin > SPECT - 1 ? SPECT - 1 : bin);
    float p = out[BSZ * SPECT + rs];
    atomicAdd(&out[b * SPECT + bin], inten * p);
}

// ---------------- launch ---------------------------------------------------
extern "C" void kernel_launch(void* const* d_in, const int* in_sizes, int n_in,
                              void* d_out, int out_size)
{
    const float* vf      = (const float*)d_in[0];
    const float* mask    = (const float*)d_in[1];
    const float* eo      = (const float*)d_in[2];
    const float* subsets = (const float*)d_in[4];
    const float* peaks   = (const float*)d_in[5];
    const float* lnsub_g = (const float*)d_in[6];
    const float* lnsub_b = (const float*)d_in[7];
    const float* W_ih    = (const float*)d_in[8];
    const float* W_hh    = (const float*)d_in[9];
    const float* b_ih    = (const float*)d_in[10];
    const float* b_hh    = (const float*)d_in[11];
    const float* W1      = (const float*)d_in[12];
    const float* b1      = (const float*)d_in[13];
    const float* W2a     = (const float*)d_in[14];
    const float* b2a     = (const float*)d_in[15];
    const float* W2b     = (const float*)d_in[16];
    const float* b2b     = (const float*)d_in[17];
    const float* lnpre_g = (const float*)d_in[18];
    const float* lnpre_b = (const float*)d_in[19];
    const float* Ws      = (const float*)d_in[20];
    const float* bsc     = (const float*)d_in[21];
    float* out = (float*)d_out;

    __half *pa, *pb, *pGHH;
    __half *whh_h, *w1_h, *w2a_h, *w2b_h;
    float* pX3;
    cudaGetSymbolAddress((void**)&pa, g_a);
    cudaGetSymbolAddress((void**)&pb, g_b);
    cudaGetSymbolAddress((void**)&pGHH, g_ghh);
    cudaGetSymbolAddress((void**)&pX3, g_x3);
    cudaGetSymbolAddress((void**)&whh_h, g_whh_h);
    cudaGetSymbolAddress((void**)&w1_h, g_w1_h);
    cudaGetSymbolAddress((void**)&w2a_h, g_w2a_h);
    cudaGetSymbolAddress((void**)&w2b_h, g_w2b_h);

    cudaMemsetAsync(d_out, 0, BSZ * SPECT * sizeof(float), 0);

    k_setup<<<(NGATE * G_N + 3 * D_N * G_N + 255) / 256, 256>>>(W_hh, W1, W2a, W2b);
    k_prefix<<<6, 256>>>(W_ih);

    cudaFuncSetAttribute(k_pre, cudaFuncAttributeMaxDynamicSharedMemorySize, 65536);
    k_pre<<<dim3(64, 16), 256, 65536>>>(vf, mask, eo, subsets, lnsub_g, lnsub_b);

    cudaFuncSetAttribute(k_mgemm<1536, 3>, cudaFuncAttributeMaxDynamicSharedMemorySize, SMEM_DYN);
    cudaFuncSetAttribute(k_mgemm<512, 1>,  cudaFuncAttributeMaxDynamicSharedMemorySize, SMEM_DYN);
    cudaFuncSetAttribute(k_mgemm<512, 2>,  cudaFuncAttributeMaxDynamicSharedMemorySize, SMEM_DYN);

    // gh = normed @ W_hh^T + b_hh  (fp16 out)
    k_mgemm<1536, 3><<<dim3(12, 512), 512, SMEM_DYN>>>(
        pa, whh_h, b_hh, nullptr, pGHH);

    // GRU combine -> h (fp16 in g_b)
    k_gru<<<BS / 4, 512>>>(b_ih);

    // MLP
    k_mgemm<512, 1><<<dim3(4, 512), 512, SMEM_DYN>>>(
        pb, w1_h, b1, nullptr, pa);
    k_mgemm<512, 1><<<dim3(4, 512), 512, SMEM_DYN>>>(
        pa, w2a_h, b2a, nullptr, pb);
    k_mgemm<512, 2><<<dim3(4, 512), 512, SMEM_DYN>>>(
        pb, w2b_h, b2b, pX3, nullptr);

    // tail
    k_lnscore<<<BS / 8, 256>>>(pX3, lnpre_g, lnpre_b, Ws, bsc);
    k_softmax<<<BSZ, 1024>>>(out);
    k_scatter<<<(BS * M_N + 255) / 256, 256>>>(peaks, out);
}